// round 8
// baseline (speedup 1.0000x reference)
#include <cuda_runtime.h>
#include <math.h>
#include <stdint.h>

#define DEV_EPS 0.025f

// ---------------- device scratch ----------------
__device__ float g_Wt[4096 * 64];         // transposed conv1 weights: [k][ch]
__device__ float g_part[16 * 4096 * 64];  // k-split GEMM partials [kz][patch][ch]
__device__ float g_s[4096];               // channel-summed metric per patch
__device__ float g_tt[4096];              // DEV_EPS + t per patch
__device__ float g_scale1[64];
__device__ float g_shift1[64];
__device__ float g_w2[64];
__device__ float g_misc[4];               // [0]=b2 [1]=scale_t [2]=shift_t

__device__ __forceinline__ float ex2a(float x) {
    float y; asm("ex2.approx.ftz.f32 %0, %1;" : "=f"(y) : "f"(x)); return y;
}
__device__ __forceinline__ float lg2a(float x) {
    float y; asm("lg2.approx.f32 %0, %1;" : "=f"(y) : "f"(x)); return y;
}
__device__ __forceinline__ void cpa16(uint32_t dst, const void* src) {
    asm volatile("cp.async.cg.shared.global [%0], [%1], 16;" :: "r"(dst), "l"(src));
}

// ---------------- prep: transpose conv1 weights to [k][ch] ----------------
__global__ void prep_wt_kernel(const float* __restrict__ conv1_w) {
    int idx = blockIdx.x * blockDim.x + threadIdx.x;
    for (; idx < 4096 * 64; idx += gridDim.x * blockDim.x) {
        int k = idx >> 6, ch = idx & 63;
        g_Wt[idx] = conv1_w[ch * 4096 + k];
    }
}

// ---------------- prep: BN folding + conv2 channel-sum ----------------
__global__ void prep_small_kernel(const float* __restrict__ conv1_b,
                                  const float* __restrict__ bn1_g,
                                  const float* __restrict__ bn1_b,
                                  const float* __restrict__ bn1_m,
                                  const float* __restrict__ bn1_v,
                                  const float* __restrict__ conv2_w,
                                  const float* __restrict__ conv2_b,
                                  const float* __restrict__ tconv_b,
                                  const float* __restrict__ bnt_g,
                                  const float* __restrict__ bnt_b,
                                  const float* __restrict__ bnt_m,
                                  const float* __restrict__ bnt_v) {
    int ch = threadIdx.x;
    if (ch < 64) {
        float inv = 1.0f / sqrtf(bn1_v[ch] + 1e-5f);
        float sc = bn1_g[ch] * inv;
        g_scale1[ch] = sc;
        g_shift1[ch] = sc * (conv1_b[ch] - bn1_m[ch]) + bn1_b[ch];
        float w2 = 0.f;
        for (int cl = 0; cl < 64; ++cl) w2 += conv2_w[cl * 64 + ch];
        g_w2[ch] = w2;
    }
    if (ch == 0) {
        float b2 = 0.f;
        for (int cl = 0; cl < 64; ++cl) b2 += conv2_b[cl];
        g_misc[0] = b2;
        float it = 1.0f / sqrtf(bnt_v[0] + 1e-5f);
        float st = bnt_g[0] * it;
        g_misc[1] = st;
        g_misc[2] = st * (tconv_b[0] - bnt_m[0]) + bnt_b[0];
    }
}

// ---------------- temperature head: matvec over K=4096 per patch ----------------
__global__ __launch_bounds__(128) void tvec_kernel(const float* __restrict__ x,
                                                   const float* __restrict__ tw) {
    __shared__ float sh[4];
    const int p = blockIdx.x;
    const int b = p >> 10, py = (p >> 5) & 31, px = p & 31;
    const float* xp = x + ((size_t)b << 22) + (py << 11) + (px << 3);
    const int t = threadIdx.x;
    float acc = 0.f;
#pragma unroll
    for (int r = 0; r < 8; ++r) {
        int u = t + 128 * r;
        int cin = u >> 4, ky = (u >> 1) & 7, kxh = u & 1;
        float4 v = *(const float4*)(xp + (cin << 16) + (ky << 8) + (kxh << 2));
        float4 w = *(const float4*)(tw + (u << 2));
        acc += v.x * w.x + v.y * w.y + v.z * w.z + v.w * w.w;
    }
#pragma unroll
    for (int o = 16; o; o >>= 1) acc += __shfl_xor_sync(0xffffffffu, acc, o);
    if ((t & 31) == 0) sh[t >> 5] = acc;
    __syncthreads();
    if (t == 0) {
        float y = sh[0] + sh[1] + sh[2] + sh[3];
        float tv = fmaxf(fmaf(g_misc[1], y, g_misc[2]), 0.f);
        g_tt[p] = DEV_EPS + tv;
    }
}

// ---------------- patch GEMM, packed f32x2 ----------------
// Grid (32 mtiles, 16 kz), 128 threads, 4 CTAs/SM (reg cap 128).
// A smem [k][128 patches]: register prefetch. One LDS.128 = 2 f32x2 patch-pairs.
// W smem [k][64] SPLIT-HALF layout per k-row (256B):
//   bytes [0,128): low 16B (ch 8c..8c+3) of octet c at offset c*16  -> quads 0..7
//   bytes [128,256): high 16B (ch 8c+4..8c+7) of octet c at 128+c*16 -> quads 0..7
//   => both W LDS.128 are conflict-free, full 128B wavefronts (was 2-way conflicted).
#define ATILE (32 * 128)
#define WTILE (32 * 64)

extern __shared__ float smg[];

__global__ __launch_bounds__(128, 4) void gemm_kernel(const float* __restrict__ x) {
    const int tid = threadIdx.x;
    const int mtile = blockIdx.x, kz = blockIdx.y;
    const int pg = tid >> 3;  // 0..15 -> patches pg*8..+7
    const int cg = tid & 7;   // 0..7  -> channels cg*8..+7

    const int p = (mtile << 7) + tid;
    const int b = p >> 10, py = (p >> 5) & 31, px = p & 31;
    const float* xp = x + ((size_t)b << 22) + (py << 11) + (px << 3);

    float* As = smg;
    float* Ws = smg + 2 * ATILE;
    uint32_t wsb;
    asm("{ .reg .u64 t; cvta.to.shared.u64 t, %1; cvt.u32.u64 %0, t; }"
        : "=r"(wsb) : "l"(Ws));

    unsigned long long acc[4][8];
#pragma unroll
    for (int q = 0; q < 4; ++q)
#pragma unroll
        for (int j = 0; j < 8; ++j) acc[q][j] = 0ull;

    float4 pa[8];
    int koff = kz << 8;

#define LDA(KO)                                                              \
    {                                                                        \
        const int _ko = (KO);                                                \
        const float* xc = xp + ((_ko >> 6) << 16) + (((_ko >> 3) & 7) << 8); \
        _Pragma("unroll")                                                    \
        for (int m = 0; m < 8; ++m)                                          \
            pa[m] = *(const float4*)(xc + ((m >> 1) << 8) + ((m & 1) << 2)); \
    }
// split-half dst mapping: unit i (k=i>>4, g=i&15; g=2c+h) -> k*256 + h*128 + c*16 bytes
#define LDW(KO, BUF)                                                            \
    {                                                                           \
        const float* wg = g_Wt + (size_t)(KO) * 64;                             \
        const uint32_t wd = wsb + (uint32_t)(BUF) * (WTILE * 4);                \
        _Pragma("unroll")                                                       \
        for (int r = 0; r < 4; ++r) {                                           \
            int i = tid + 128 * r;                                              \
            int kk = i >> 4, g = i & 15;                                        \
            uint32_t dst = wd + (uint32_t)((kk << 8) + ((g & 1) << 7) + ((g >> 1) << 4)); \
            cpa16(dst, wg + i * 4);                                             \
        }                                                                       \
        asm volatile("cp.async.commit_group;");                                 \
    }

    LDA(koff);
    LDW(koff, 0);

    for (int cc = 0; cc < 8; ++cc) {
        float* A = As + (cc & 1) * ATILE;
        float* W = Ws + (cc & 1) * WTILE;
#pragma unroll
        for (int m = 0; m < 8; ++m) {
            int kl = ((m >> 1) << 3) + ((m & 1) << 2);
            A[(kl + 0) * 128 + tid] = pa[m].x;
            A[(kl + 1) * 128 + tid] = pa[m].y;
            A[(kl + 2) * 128 + tid] = pa[m].z;
            A[(kl + 3) * 128 + tid] = pa[m].w;
        }
        asm volatile("cp.async.wait_group 0;");
        __syncthreads();

        if (cc < 7) {
            LDA(koff + 32);
            LDW(koff + 32, (cc + 1) & 1);
        }
        koff += 32;

#pragma unroll 2
        for (int k = 0; k < 32; ++k) {
            const float* ar = &A[(k << 7) + (pg << 3)];
            longlong2 a0 = *(const longlong2*)ar;
            longlong2 a1 = *(const longlong2*)(ar + 4);
            // split-half W reads: w0 = ch cg*8..+3, w1 = ch cg*8+4..+7
            const float* wr = &W[(k << 6) + (cg << 2)];
            float4 w0 = *(const float4*)wr;
            float4 w1 = *(const float4*)(wr + 32);
            unsigned long long aq[4];
            aq[0] = (unsigned long long)a0.x;
            aq[1] = (unsigned long long)a0.y;
            aq[2] = (unsigned long long)a1.x;
            aq[3] = (unsigned long long)a1.y;
            unsigned long long wd[8];
            uint32_t wb[8] = {__float_as_uint(w0.x), __float_as_uint(w0.y),
                              __float_as_uint(w0.z), __float_as_uint(w0.w),
                              __float_as_uint(w1.x), __float_as_uint(w1.y),
                              __float_as_uint(w1.z), __float_as_uint(w1.w)};
#pragma unroll
            for (int j = 0; j < 8; ++j)
                asm("mov.b64 %0, {%1, %1};" : "=l"(wd[j]) : "r"(wb[j]));
#pragma unroll
            for (int q = 0; q < 4; ++q)
#pragma unroll
                for (int j = 0; j < 8; ++j)
                    asm("fma.rn.f32x2 %0, %1, %2, %0;"
                        : "+l"(acc[q][j]) : "l"(aq[q]), "l"(wd[j]));
        }
        __syncthreads();
    }

    // store: acc[q][j] = (patch 2q, patch 2q+1) for channel cg*8+j
#pragma unroll
    for (int q = 0; q < 4; ++q) {
        int p0 = (mtile << 7) + (pg << 3) + 2 * q;
        float* d0 = g_part + ((size_t)kz * 4096 + p0) * 64 + (cg << 3);
        float* d1 = d0 + 64;
        float4 lo0, lo1, hi0, hi1;
        lo0.x = __uint_as_float((uint32_t)acc[q][0]);
        lo0.y = __uint_as_float((uint32_t)acc[q][1]);
        lo0.z = __uint_as_float((uint32_t)acc[q][2]);
        lo0.w = __uint_as_float((uint32_t)acc[q][3]);
        lo1.x = __uint_as_float((uint32_t)acc[q][4]);
        lo1.y = __uint_as_float((uint32_t)acc[q][5]);
        lo1.z = __uint_as_float((uint32_t)acc[q][6]);
        lo1.w = __uint_as_float((uint32_t)acc[q][7]);
        hi0.x = __uint_as_float((uint32_t)(acc[q][0] >> 32));
        hi0.y = __uint_as_float((uint32_t)(acc[q][1] >> 32));
        hi0.z = __uint_as_float((uint32_t)(acc[q][2] >> 32));
        hi0.w = __uint_as_float((uint32_t)(acc[q][3] >> 32));
        hi1.x = __uint_as_float((uint32_t)(acc[q][4] >> 32));
        hi1.y = __uint_as_float((uint32_t)(acc[q][5] >> 32));
        hi1.z = __uint_as_float((uint32_t)(acc[q][6] >> 32));
        hi1.w = __uint_as_float((uint32_t)(acc[q][7] >> 32));
        *(float4*)d0 = lo0;
        *(float4*)(d0 + 4) = lo1;
        *(float4*)d1 = hi0;
        *(float4*)(d1 + 4) = hi1;
    }
}

// ---------------- epilogue: k-split reduce + BN + ReLU + channel reduce ----------------
__global__ __launch_bounds__(256) void epi_kernel() {
    int p = blockIdx.x * 8 + (threadIdx.x >> 5);
    int lane = threadIdx.x & 31;
    float y0 = 0.f, y1 = 0.f;
#pragma unroll
    for (int kz = 0; kz < 16; ++kz) {
        const float* base = g_part + ((size_t)kz * 4096 + p) * 64;
        y0 += base[lane];
        y1 += base[lane + 32];
    }
    float v = fmaxf(fmaf(g_scale1[lane], y0, g_shift1[lane]), 0.f) * g_w2[lane] +
              fmaxf(fmaf(g_scale1[lane + 32], y1, g_shift1[lane + 32]), 0.f) * g_w2[lane + 32];
#pragma unroll
    for (int o = 16; o; o >>= 1) v += __shfl_xor_sync(0xffffffffu, v, o);
    if (lane == 0) g_s[p] = v + g_misc[0];
}

// ---------------- softmax: warp-per-row, register logits, MUFU fast path ----------------
__global__ __launch_bounds__(256) void softmax_kernel(float* __restrict__ out) {
    const int w = threadIdx.x >> 5, lane = threadIdx.x & 31;
    const int r = blockIdx.x * 8 + w;
    const int b = r >> 10, i = r & 1023;
    const float si = g_s[r];
    const float invt = 1.0f / g_tt[r];
    const float c = invt * 1.4426950408889634f;

    float l2[32];
#pragma unroll
    for (int q = 0; q < 8; ++q) {
        int j = (q << 7) + (lane << 2);
        float4 s4 = *(const float4*)(g_s + (b << 10) + j);
        float sv[4] = {s4.x, s4.y, s4.z, s4.w};
#pragma unroll
        for (int u = 0; u < 4; ++u) {
            float d = si - sv[u];
            float val = -d * d;
            if (j + u == i) val -= 1000.0f;
            l2[q * 4 + u] = val * c;
        }
    }

    const size_t rbase = ((size_t)b << 20) + ((size_t)i << 10);
#pragma unroll 1
    for (int it = 0; it < 4; ++it) {
        float m = l2[0];
#pragma unroll
        for (int q = 1; q < 32; ++q) m = fmaxf(m, l2[q]);
#pragma unroll
        for (int o = 16; o; o >>= 1) m = fmaxf(m, __shfl_xor_sync(0xffffffffu, m, o));
        float e[32];
        float s = 0.f;
#pragma unroll
        for (int q = 0; q < 32; ++q) {
            e[q] = ex2a(l2[q] - m);
            s += e[q];
        }
#pragma unroll
        for (int o = 16; o; o >>= 1) s += __shfl_xor_sync(0xffffffffu, s, o);
        float invS = 1.0f / s;
        float* op = out + (((size_t)it) << 22) + rbase + (lane << 2);
#pragma unroll
        for (int q = 0; q < 8; ++q) {
            float4 po;
            po.x = e[q * 4 + 0] * invS;
            po.y = e[q * 4 + 1] * invS;
            po.z = e[q * 4 + 2] * invS;
            po.w = e[q * 4 + 3] * invS;
            __stcs((float4*)(op + (q << 7)), po);
        }
        if (it < 3) {
#pragma unroll
            for (int q = 0; q < 32; ++q) {
                float pr = e[q] * invS;
                float om = fmaxf(1.0f - pr, 1e-38f);
                l2[q] += lg2a(om) * invt;
            }
        }
    }
}

// ---------------- launch ----------------
extern "C" void kernel_launch(void* const* d_in, const int* in_sizes, int n_in,
                              void* d_out, int out_size) {
    const float* x = (const float*)d_in[0];
    const float* conv1_w = (const float*)d_in[1];
    const float* conv1_b = (const float*)d_in[2];
    const float* bn1_g = (const float*)d_in[3];
    const float* bn1_b = (const float*)d_in[4];
    const float* bn1_m = (const float*)d_in[5];
    const float* bn1_v = (const float*)d_in[6];
    const float* conv2_w = (const float*)d_in[7];
    const float* conv2_b = (const float*)d_in[8];
    const float* tconv_w = (const float*)d_in[9];
    const float* tconv_b = (const float*)d_in[10];
    const float* bnt_g = (const float*)d_in[11];
    const float* bnt_b = (const float*)d_in[12];
    const float* bnt_m = (const float*)d_in[13];
    const float* bnt_v = (const float*)d_in[14];
    float* out = (float*)d_out;

    static int smem_set = 0;
    const int dyn_smem = (2 * ATILE + 2 * WTILE) * 4;  // 49152 B
    if (!smem_set) {
        cudaFuncSetAttribute(gemm_kernel,
                             cudaFuncAttributeMaxDynamicSharedMemorySize, dyn_smem);
        smem_set = 1;
    }

    prep_wt_kernel<<<256, 256>>>(conv1_w);
    prep_small_kernel<<<1, 64>>>(conv1_b, bn1_g, bn1_b, bn1_m, bn1_v,
                                 conv2_w, conv2_b, tconv_b, bnt_g, bnt_b, bnt_m, bnt_v);
    tvec_kernel<<<4096, 128>>>(x, tconv_w);
    dim3 g(32, 16);
    gemm_kernel<<<g, 128, dyn_smem>>>(x);
    epi_kernel<<<512, 256>>>();
    softmax_kernel<<<512, 256>>>(out);
}

// round 10
// speedup vs baseline: 1.1940x; 1.1940x over previous
#include <cuda_runtime.h>
#include <math.h>
#include <stdint.h>

#define DEV_EPS 0.025f

// ---------------- device scratch ----------------
__device__ float g_Wd[4096 * 128];        // dup'd weights: [k][128] = (w,w) pairs, quad-interleaved
__device__ float g_part[16 * 4096 * 64];  // k-split GEMM partials [kz][patch][ch]
__device__ float g_pt[16 * 4096];         // k-split tconv partials [kz][patch]
__device__ float g_s[4096];               // channel-summed metric per patch
__device__ float g_tt[4096];              // DEV_EPS + t per patch
__device__ float g_scale1[64];
__device__ float g_shift1[64];
__device__ float g_w2[64];
__device__ float g_misc[4];               // [0]=b2 [1]=scale_t [2]=shift_t

__device__ __forceinline__ float ex2a(float x) {
    float y; asm("ex2.approx.ftz.f32 %0, %1;" : "=f"(y) : "f"(x)); return y;
}
__device__ __forceinline__ float lg2a(float x) {
    float y; asm("lg2.approx.f32 %0, %1;" : "=f"(y) : "f"(x)); return y;
}
__device__ __forceinline__ void cpa16(uint32_t dst, const void* src) {
    asm volatile("cp.async.cg.shared.global [%0], [%1], 16;" :: "r"(dst), "l"(src));
}

// ---------------- prep: duplicate+interleave conv1 weights ----------------
// g_Wd[k*128 + q*32 + cg*4 + e] = conv1_w[(8cg + 2q + (e>>1)) * 4096 + k]
__global__ void prep_wd_kernel(const float* __restrict__ conv1_w) {
    int idx = blockIdx.x * blockDim.x + threadIdx.x;  // 524288
    int k = idx >> 7, f = idx & 127;
    int q = f >> 5, cg = (f >> 2) & 7, e = f & 3;
    int ch = 8 * cg + 2 * q + (e >> 1);
    g_Wd[idx] = conv1_w[ch * 4096 + k];
}

// ---------------- prep: BN folding + conv2 channel-sum ----------------
__global__ void prep_small_kernel(const float* __restrict__ conv1_b,
                                  const float* __restrict__ bn1_g,
                                  const float* __restrict__ bn1_b,
                                  const float* __restrict__ bn1_m,
                                  const float* __restrict__ bn1_v,
                                  const float* __restrict__ conv2_w,
                                  const float* __restrict__ conv2_b,
                                  const float* __restrict__ tconv_b,
                                  const float* __restrict__ bnt_g,
                                  const float* __restrict__ bnt_b,
                                  const float* __restrict__ bnt_m,
                                  const float* __restrict__ bnt_v) {
    int ch = threadIdx.x;
    if (ch < 64) {
        float inv = 1.0f / sqrtf(bn1_v[ch] + 1e-5f);
        float sc = bn1_g[ch] * inv;
        g_scale1[ch] = sc;
        g_shift1[ch] = sc * (conv1_b[ch] - bn1_m[ch]) + bn1_b[ch];
        float w2 = 0.f;
        for (int cl = 0; cl < 64; ++cl) w2 += conv2_w[cl * 64 + ch];
        g_w2[ch] = w2;
    }
    if (ch == 0) {
        float b2 = 0.f;
        for (int cl = 0; cl < 64; ++cl) b2 += conv2_b[cl];
        g_misc[0] = b2;
        float it = 1.0f / sqrtf(bnt_v[0] + 1e-5f);
        float st = bnt_g[0] * it;
        g_misc[1] = st;
        g_misc[2] = st * (tconv_b[0] - bnt_m[0]) + bnt_b[0];
    }
}

// ---------------- patch GEMM + fused temperature head ----------------
// Grid (32 mtiles, 16 kz), 128 threads, 4 CTAs/SM.
// 16 chunks of 16 k. A smem [k][128] (reg prefetch), W smem [k][128] dup'd (cp.async).
// Inner k: 2 A LDS.128 + 4 W LDS.128 + 32 FFMA2 (no MOVs).
#define ATILE (16 * 128)
#define WTILE (16 * 128)
#define TWOFF (2 * ATILE + 2 * WTILE)
#define DYN_SMEM ((TWOFF + 256) * 4)  // 33792 B

extern __shared__ float smg[];

__global__ __launch_bounds__(128, 4) void gemm_kernel(const float* __restrict__ x,
                                                      const float* __restrict__ tw) {
    const int tid = threadIdx.x;
    const int mtile = blockIdx.x, kz = blockIdx.y;
    const int pg = tid >> 3;  // 0..15 -> patches pg*8..+7
    const int cg = tid & 7;   // 0..7  -> channels cg*8..+7

    const int p = (mtile << 7) + tid;
    const int b = p >> 10, py = (p >> 5) & 31, px = p & 31;
    const float* xp = x + ((size_t)b << 22) + (py << 11) + (px << 3);

    float* As = smg;
    float* Ws = smg + 2 * ATILE;
    float* tws = smg + TWOFF;
    uint32_t wsb, twb;
    asm("{ .reg .u64 t; cvta.to.shared.u64 t, %1; cvt.u32.u64 %0, t; }"
        : "=r"(wsb) : "l"(Ws));
    asm("{ .reg .u64 t; cvta.to.shared.u64 t, %1; cvt.u32.u64 %0, t; }"
        : "=r"(twb) : "l"(tws));

    unsigned long long acc[4][8];
#pragma unroll
    for (int q = 0; q < 4; ++q)
#pragma unroll
        for (int j = 0; j < 8; ++j) acc[q][j] = 0ull;
    float tacc = 0.f;

    float4 pa[4];
    int koff = kz << 8;

#define LDA(KO)                                                              \
    {                                                                        \
        const int _ko = (KO);                                                \
        const float* xc = xp + ((_ko >> 6) << 16) + (((_ko >> 3) & 7) << 8); \
        _Pragma("unroll")                                                    \
        for (int m = 0; m < 4; ++m)                                          \
            pa[m] = *(const float4*)(xc + ((m >> 1) << 8) + ((m & 1) << 2)); \
    }
#define LDW(KO, BUF)                                                         \
    {                                                                        \
        const float* wg = g_Wd + (size_t)(KO) * 128;                         \
        const uint32_t wd = wsb + (uint32_t)(BUF) * (WTILE * 4);             \
        _Pragma("unroll")                                                    \
        for (int r = 0; r < 4; ++r)                                          \
            cpa16(wd + (uint32_t)(tid + 128 * r) * 16u, wg + (tid + 128 * r) * 4); \
        asm volatile("cp.async.commit_group;");                              \
    }

    LDA(koff);
    // tw slice FIRST so it joins LDW's commit group (G0) and is waited before cc=0 use.
    if (tid < 64) cpa16(twb + (uint32_t)tid * 16u, tw + (kz << 8) + tid * 4);
    LDW(koff, 0);

    for (int cc = 0; cc < 16; ++cc) {
        float* A = As + (cc & 1) * ATILE;
        float* W = Ws + (cc & 1) * WTILE;
#pragma unroll
        for (int m = 0; m < 4; ++m) {
            int kl = ((m >> 1) << 3) + ((m & 1) << 2);
            A[(kl + 0) * 128 + tid] = pa[m].x;
            A[(kl + 1) * 128 + tid] = pa[m].y;
            A[(kl + 2) * 128 + tid] = pa[m].z;
            A[(kl + 3) * 128 + tid] = pa[m].w;
        }
        asm volatile("cp.async.wait_group 0;");
        __syncthreads();

        // fused temperature dot: uses this chunk's pa before it is overwritten
        {
            const float* twc = tws + (cc << 4);
#pragma unroll
            for (int m = 0; m < 4; ++m) {
                int kl = ((m >> 1) << 3) + ((m & 1) << 2);
                tacc = fmaf(pa[m].x, twc[kl + 0], tacc);
                tacc = fmaf(pa[m].y, twc[kl + 1], tacc);
                tacc = fmaf(pa[m].z, twc[kl + 2], tacc);
                tacc = fmaf(pa[m].w, twc[kl + 3], tacc);
            }
        }

        if (cc < 15) {
            LDA(koff + 16);
            LDW(koff + 16, (cc + 1) & 1);
        }
        koff += 16;

#pragma unroll 4
        for (int k = 0; k < 16; ++k) {
            const float* ar = &A[(k << 7) + (pg << 3)];
            ulonglong2 a01 = *(const ulonglong2*)ar;
            ulonglong2 a23 = *(const ulonglong2*)(ar + 4);
            const float* wr = &W[(k << 7) + (cg << 2)];
            ulonglong2 wq0 = *(const ulonglong2*)wr;
            ulonglong2 wq1 = *(const ulonglong2*)(wr + 32);
            ulonglong2 wq2 = *(const ulonglong2*)(wr + 64);
            ulonglong2 wq3 = *(const ulonglong2*)(wr + 96);
            unsigned long long aq[4] = {a01.x, a01.y, a23.x, a23.y};
            unsigned long long wp[8] = {wq0.x, wq0.y, wq1.x, wq1.y,
                                        wq2.x, wq2.y, wq3.x, wq3.y};
#pragma unroll
            for (int q = 0; q < 4; ++q)
#pragma unroll
                for (int j = 0; j < 8; ++j)
                    asm("fma.rn.f32x2 %0, %1, %2, %0;"
                        : "+l"(acc[q][j]) : "l"(aq[q]), "l"(wp[j]));
        }
    }

    // store GEMM partials: acc[q][j] = (patch 2q, 2q+1) of pg*8, channel cg*8+j
#pragma unroll
    for (int q = 0; q < 4; ++q) {
        int p0 = (mtile << 7) + (pg << 3) + 2 * q;
        float* d0 = g_part + ((size_t)kz * 4096 + p0) * 64 + (cg << 3);
        float* d1 = d0 + 64;
        float4 lo0, lo1, hi0, hi1;
        lo0.x = __uint_as_float((uint32_t)acc[q][0]);
        lo0.y = __uint_as_float((uint32_t)acc[q][1]);
        lo0.z = __uint_as_float((uint32_t)acc[q][2]);
        lo0.w = __uint_as_float((uint32_t)acc[q][3]);
        lo1.x = __uint_as_float((uint32_t)acc[q][4]);
        lo1.y = __uint_as_float((uint32_t)acc[q][5]);
        lo1.z = __uint_as_float((uint32_t)acc[q][6]);
        lo1.w = __uint_as_float((uint32_t)acc[q][7]);
        hi0.x = __uint_as_float((uint32_t)(acc[q][0] >> 32));
        hi0.y = __uint_as_float((uint32_t)(acc[q][1] >> 32));
        hi0.z = __uint_as_float((uint32_t)(acc[q][2] >> 32));
        hi0.w = __uint_as_float((uint32_t)(acc[q][3] >> 32));
        hi1.x = __uint_as_float((uint32_t)(acc[q][4] >> 32));
        hi1.y = __uint_as_float((uint32_t)(acc[q][5] >> 32));
        hi1.z = __uint_as_float((uint32_t)(acc[q][6] >> 32));
        hi1.w = __uint_as_float((uint32_t)(acc[q][7] >> 32));
        *(float4*)d0 = lo0;
        *(float4*)(d0 + 4) = lo1;
        *(float4*)d1 = hi0;
        *(float4*)(d1 + 4) = hi1;
    }
    g_pt[kz * 4096 + p] = tacc;
}

// ---------------- epilogue: k-split reduce + BN + ReLU + channel reduce + t ----------------
__global__ __launch_bounds__(256) void epi_kernel() {
    int p = blockIdx.x * 8 + (threadIdx.x >> 5);
    int lane = threadIdx.x & 31;
    float y0 = 0.f, y1 = 0.f;
#pragma unroll
    for (int kz = 0; kz < 16; ++kz) {
        const float* base = g_part + ((size_t)kz * 4096 + p) * 64;
        y0 += base[lane];
        y1 += base[lane + 32];
    }
    float v = fmaxf(fmaf(g_scale1[lane], y0, g_shift1[lane]), 0.f) * g_w2[lane] +
              fmaxf(fmaf(g_scale1[lane + 32], y1, g_shift1[lane + 32]), 0.f) * g_w2[lane + 32];
    float tv = (lane < 16) ? g_pt[lane * 4096 + p] : 0.f;
#pragma unroll
    for (int o = 16; o; o >>= 1) {
        v += __shfl_xor_sync(0xffffffffu, v, o);
        tv += __shfl_xor_sync(0xffffffffu, tv, o);
    }
    if (lane == 0) {
        g_s[p] = v + g_misc[0];
        float t = fmaxf(fmaf(g_misc[1], tv, g_misc[2]), 0.f);
        g_tt[p] = DEV_EPS + t;
    }
}

// ---------------- softmax: warp-per-row, register logits, MUFU fast path ----------------
__global__ __launch_bounds__(256) void softmax_kernel(float* __restrict__ out) {
    const int w = threadIdx.x >> 5, lane = threadIdx.x & 31;
    const int r = blockIdx.x * 8 + w;
    const int b = r >> 10, i = r & 1023;
    const float si = g_s[r];
    const float invt = 1.0f / g_tt[r];
    const float c = invt * 1.4426950408889634f;

    float l2[32];
#pragma unroll
    for (int q = 0; q < 8; ++q) {
        int j = (q << 7) + (lane << 2);
        float4 s4 = *(const float4*)(g_s + (b << 10) + j);
        float sv[4] = {s4.x, s4.y, s4.z, s4.w};
#pragma unroll
        for (int u = 0; u < 4; ++u) {
            float d = si - sv[u];
            float val = -d * d;
            if (j + u == i) val -= 1000.0f;
            l2[q * 4 + u] = val * c;
        }
    }

    const size_t rbase = ((size_t)b << 20) + ((size_t)i << 10);
#pragma unroll 1
    for (int it = 0; it < 4; ++it) {
        float m = l2[0];
#pragma unroll
        for (int q = 1; q < 32; ++q) m = fmaxf(m, l2[q]);
#pragma unroll
        for (int o = 16; o; o >>= 1) m = fmaxf(m, __shfl_xor_sync(0xffffffffu, m, o));
        float e[32];
        float s = 0.f;
#pragma unroll
        for (int q = 0; q < 32; ++q) {
            e[q] = ex2a(l2[q] - m);
            s += e[q];
        }
#pragma unroll
        for (int o = 16; o; o >>= 1) s += __shfl_xor_sync(0xffffffffu, s, o);
        float invS = 1.0f / s;
        float* op = out + (((size_t)it) << 22) + rbase + (lane << 2);
#pragma unroll
        for (int q = 0; q < 8; ++q) {
            float4 po;
            po.x = e[q * 4 + 0] * invS;
            po.y = e[q * 4 + 1] * invS;
            po.z = e[q * 4 + 2] * invS;
            po.w = e[q * 4 + 3] * invS;
            __stcs((float4*)(op + (q << 7)), po);
        }
        if (it < 3) {
#pragma unroll
            for (int q = 0; q < 32; ++q) {
                float pr = e[q] * invS;
                float om = fmaxf(1.0f - pr, 1e-38f);
                l2[q] += lg2a(om) * invt;
            }
        }
    }
}

// ---------------- launch ----------------
extern "C" void kernel_launch(void* const* d_in, const int* in_sizes, int n_in,
                              void* d_out, int out_size) {
    const float* x = (const float*)d_in[0];
    const float* conv1_w = (const float*)d_in[1];
    const float* conv1_b = (const float*)d_in[2];
    const float* bn1_g = (const float*)d_in[3];
    const float* bn1_b = (const float*)d_in[4];
    const float* bn1_m = (const float*)d_in[5];
    const float* bn1_v = (const float*)d_in[6];
    const float* conv2_w = (const float*)d_in[7];
    const float* conv2_b = (const float*)d_in[8];
    const float* tconv_w = (const float*)d_in[9];
    const float* tconv_b = (const float*)d_in[10];
    const float* bnt_g = (const float*)d_in[11];
    const float* bnt_b = (const float*)d_in[12];
    const float* bnt_m = (const float*)d_in[13];
    const float* bnt_v = (const float*)d_in[14];
    float* out = (float*)d_out;

    static int smem_set = 0;
    if (!smem_set) {
        cudaFuncSetAttribute(gemm_kernel,
                             cudaFuncAttributeMaxDynamicSharedMemorySize, DYN_SMEM);
        smem_set = 1;
    }

    prep_wd_kernel<<<2048, 256>>>(conv1_w);
    prep_small_kernel<<<1, 64>>>(conv1_b, bn1_g, bn1_b, bn1_m, bn1_v,
                                 conv2_w, conv2_b, tconv_b, bnt_g, bnt_b, bnt_m, bnt_v);
    dim3 g(32, 16);
    gemm_kernel<<<g, 128, DYN_SMEM>>>(x, tconv_w);
    epi_kernel<<<512, 256>>>();
    softmax_kernel<<<512, 256>>>(out);
}

// round 12
// speedup vs baseline: 1.1960x; 1.0017x over previous
#include <cuda_runtime.h>
#include <math.h>
#include <stdint.h>

#define DEV_EPS 0.025f

// ---------------- device scratch ----------------
__device__ float g_Wd[4096 * 128];        // dup'd weights: [k][128] = (w,w) pairs, quad-interleaved
__device__ float g_part[16 * 4096 * 64];  // k-split GEMM partials [kz][patch][ch]
__device__ float g_pt[16 * 4096];         // k-split tconv partials [kz][patch]
__device__ float g_s[4096];               // channel-summed metric per patch
__device__ float g_tt[4096];              // DEV_EPS + t per patch
__device__ float g_scale1[64];
__device__ float g_shift1[64];
__device__ float g_w2[64];
__device__ float g_misc[4];               // [0]=b2 [1]=scale_t [2]=shift_t

__device__ __forceinline__ float ex2a(float x) {
    float y; asm("ex2.approx.ftz.f32 %0, %1;" : "=f"(y) : "f"(x)); return y;
}
__device__ __forceinline__ float lg2a(float x) {
    float y; asm("lg2.approx.f32 %0, %1;" : "=f"(y) : "f"(x)); return y;
}
__device__ __forceinline__ void cpa16(uint32_t dst, const void* src) {
    asm volatile("cp.async.cg.shared.global [%0], [%1], 16;" :: "r"(dst), "l"(src));
}

// ---------------- prep: duplicate+interleave conv1 weights ----------------
__global__ void prep_wd_kernel(const float* __restrict__ conv1_w) {
    int idx = blockIdx.x * blockDim.x + threadIdx.x;  // 524288
    int k = idx >> 7, f = idx & 127;
    int q = f >> 5, cg = (f >> 2) & 7, e = f & 3;
    int ch = 8 * cg + 2 * q + (e >> 1);
    g_Wd[idx] = conv1_w[ch * 4096 + k];
}

// ---------------- prep: BN folding + conv2 channel-sum ----------------
__global__ void prep_small_kernel(const float* __restrict__ conv1_b,
                                  const float* __restrict__ bn1_g,
                                  const float* __restrict__ bn1_b,
                                  const float* __restrict__ bn1_m,
                                  const float* __restrict__ bn1_v,
                                  const float* __restrict__ conv2_w,
                                  const float* __restrict__ conv2_b,
                                  const float* __restrict__ tconv_b,
                                  const float* __restrict__ bnt_g,
                                  const float* __restrict__ bnt_b,
                                  const float* __restrict__ bnt_m,
                                  const float* __restrict__ bnt_v) {
    int ch = threadIdx.x;
    if (ch < 64) {
        float inv = 1.0f / sqrtf(bn1_v[ch] + 1e-5f);
        float sc = bn1_g[ch] * inv;
        g_scale1[ch] = sc;
        g_shift1[ch] = sc * (conv1_b[ch] - bn1_m[ch]) + bn1_b[ch];
        float w2 = 0.f;
        for (int cl = 0; cl < 64; ++cl) w2 += conv2_w[cl * 64 + ch];
        g_w2[ch] = w2;
    }
    if (ch == 0) {
        float b2 = 0.f;
        for (int cl = 0; cl < 64; ++cl) b2 += conv2_b[cl];
        g_misc[0] = b2;
        float it = 1.0f / sqrtf(bnt_v[0] + 1e-5f);
        float st = bnt_g[0] * it;
        g_misc[1] = st;
        g_misc[2] = st * (tconv_b[0] - bnt_m[0]) + bnt_b[0];
    }
}

// ---------------- patch GEMM + fused temperature head ----------------
// Grid (32 mtiles, 16 kz), 128 threads, 4 CTAs/SM.
// 16 chunks of 16 k. A smem [k][128] (reg prefetch), W smem [k][128] dup'd (cp.async).
// Inner k: 2 A LDS.128 + 4 W LDS.128 + 32 FFMA2 (no MOVs).
#define ATILE (16 * 128)
#define WTILE (16 * 128)
#define TWOFF (2 * ATILE + 2 * WTILE)
#define DYN_SMEM ((TWOFF + 256) * 4)  // 33792 B

extern __shared__ float smg[];

__global__ __launch_bounds__(128, 4) void gemm_kernel(const float* __restrict__ x,
                                                      const float* __restrict__ tw) {
    const int tid = threadIdx.x;
    const int mtile = blockIdx.x, kz = blockIdx.y;
    const int pg = tid >> 3;  // 0..15 -> patches pg*8..+7
    const int cg = tid & 7;   // 0..7  -> channels cg*8..+7

    const int p = (mtile << 7) + tid;
    const int b = p >> 10, py = (p >> 5) & 31, px = p & 31;
    const float* xp = x + ((size_t)b << 22) + (py << 11) + (px << 3);

    float* As = smg;
    float* Ws = smg + 2 * ATILE;
    float* tws = smg + TWOFF;
    uint32_t wsb, twb;
    asm("{ .reg .u64 t; cvta.to.shared.u64 t, %1; cvt.u32.u64 %0, t; }"
        : "=r"(wsb) : "l"(Ws));
    asm("{ .reg .u64 t; cvta.to.shared.u64 t, %1; cvt.u32.u64 %0, t; }"
        : "=r"(twb) : "l"(tws));

    unsigned long long acc[4][8];
#pragma unroll
    for (int q = 0; q < 4; ++q)
#pragma unroll
        for (int j = 0; j < 8; ++j) acc[q][j] = 0ull;
    float tacc = 0.f;

    float4 pa[4];
    int koff = kz << 8;

#define LDA(KO)                                                              \
    {                                                                        \
        const int _ko = (KO);                                                \
        const float* xc = xp + ((_ko >> 6) << 16) + (((_ko >> 3) & 7) << 8); \
        _Pragma("unroll")                                                    \
        for (int m = 0; m < 4; ++m)                                          \
            pa[m] = *(const float4*)(xc + ((m >> 1) << 8) + ((m & 1) << 2)); \
    }
#define LDW(KO, BUF)                                                         \
    {                                                                        \
        const float* wg = g_Wd + (size_t)(KO) * 128;                         \
        const uint32_t wd = wsb + (uint32_t)(BUF) * (WTILE * 4);             \
        _Pragma("unroll")                                                    \
        for (int r = 0; r < 4; ++r)                                          \
            cpa16(wd + (uint32_t)(tid + 128 * r) * 16u, wg + (tid + 128 * r) * 4); \
        asm volatile("cp.async.commit_group;");                              \
    }

    LDA(koff);
    // tw slice FIRST so it joins LDW's commit group (G0), waited before cc=0 use.
    if (tid < 64) cpa16(twb + (uint32_t)tid * 16u, tw + (kz << 8) + tid * 4);
    LDW(koff, 0);

    for (int cc = 0; cc < 16; ++cc) {
        float* A = As + (cc & 1) * ATILE;
        float* W = Ws + (cc & 1) * WTILE;
#pragma unroll
        for (int m = 0; m < 4; ++m) {
            int kl = ((m >> 1) << 3) + ((m & 1) << 2);
            A[(kl + 0) * 128 + tid] = pa[m].x;
            A[(kl + 1) * 128 + tid] = pa[m].y;
            A[(kl + 2) * 128 + tid] = pa[m].z;
            A[(kl + 3) * 128 + tid] = pa[m].w;
        }
        asm volatile("cp.async.wait_group 0;");
        __syncthreads();

        // fused temperature dot: uses this chunk's pa before it is overwritten
        {
            const float* twc = tws + (cc << 4);
#pragma unroll
            for (int m = 0; m < 4; ++m) {
                int kl = ((m >> 1) << 3) + ((m & 1) << 2);
                tacc = fmaf(pa[m].x, twc[kl + 0], tacc);
                tacc = fmaf(pa[m].y, twc[kl + 1], tacc);
                tacc = fmaf(pa[m].z, twc[kl + 2], tacc);
                tacc = fmaf(pa[m].w, twc[kl + 3], tacc);
            }
        }

        if (cc < 15) {
            LDA(koff + 16);
            LDW(koff + 16, (cc + 1) & 1);
        }
        koff += 16;

#pragma unroll 8
        for (int k = 0; k < 16; ++k) {
            const float* ar = &A[(k << 7) + (pg << 3)];
            ulonglong2 a01 = *(const ulonglong2*)ar;
            ulonglong2 a23 = *(const ulonglong2*)(ar + 4);
            const float* wr = &W[(k << 7) + (cg << 2)];
            ulonglong2 wq0 = *(const ulonglong2*)wr;
            ulonglong2 wq1 = *(const ulonglong2*)(wr + 32);
            ulonglong2 wq2 = *(const ulonglong2*)(wr + 64);
            ulonglong2 wq3 = *(const ulonglong2*)(wr + 96);
            unsigned long long aq[4] = {a01.x, a01.y, a23.x, a23.y};
            unsigned long long wp[8] = {wq0.x, wq0.y, wq1.x, wq1.y,
                                        wq2.x, wq2.y, wq3.x, wq3.y};
#pragma unroll
            for (int q = 0; q < 4; ++q)
#pragma unroll
                for (int j = 0; j < 8; ++j)
                    asm("fma.rn.f32x2 %0, %1, %2, %0;"
                        : "+l"(acc[q][j]) : "l"(aq[q]), "l"(wp[j]));
        }
    }

    // store GEMM partials: acc[q][j] = (patch 2q, 2q+1) of pg*8, channel cg*8+j
#pragma unroll
    for (int q = 0; q < 4; ++q) {
        int p0 = (mtile << 7) + (pg << 3) + 2 * q;
        float* d0 = g_part + ((size_t)kz * 4096 + p0) * 64 + (cg << 3);
        float* d1 = d0 + 64;
        float4 lo0, lo1, hi0, hi1;
        lo0.x = __uint_as_float((uint32_t)acc[q][0]);
        lo0.y = __uint_as_float((uint32_t)acc[q][1]);
        lo0.z = __uint_as_float((uint32_t)acc[q][2]);
        lo0.w = __uint_as_float((uint32_t)acc[q][3]);
        lo1.x = __uint_as_float((uint32_t)acc[q][4]);
        lo1.y = __uint_as_float((uint32_t)acc[q][5]);
        lo1.z = __uint_as_float((uint32_t)acc[q][6]);
        lo1.w = __uint_as_float((uint32_t)acc[q][7]);
        hi0.x = __uint_as_float((uint32_t)(acc[q][0] >> 32));
        hi0.y = __uint_as_float((uint32_t)(acc[q][1] >> 32));
        hi0.z = __uint_as_float((uint32_t)(acc[q][2] >> 32));
        hi0.w = __uint_as_float((uint32_t)(acc[q][3] >> 32));
        hi1.x = __uint_as_float((uint32_t)(acc[q][4] >> 32));
        hi1.y = __uint_as_float((uint32_t)(acc[q][5] >> 32));
        hi1.z = __uint_as_float((uint32_t)(acc[q][6] >> 32));
        hi1.w = __uint_as_float((uint32_t)(acc[q][7] >> 32));
        *(float4*)d0 = lo0;
        *(float4*)(d0 + 4) = lo1;
        *(float4*)d1 = hi0;
        *(float4*)(d1 + 4) = hi1;
    }
    g_pt[kz * 4096 + p] = tacc;
}

// ---------------- epilogue: MLP-16 k-split reduce + BN + ReLU + reduce + t ----------
// 256 threads, 8 warps; half-warp per patch (16 lanes x 4 channels = 64 ch).
__global__ __launch_bounds__(256) void epi_kernel() {
    const int tid = threadIdx.x;
    const int warp = tid >> 5, lane = tid & 31;
    const int half = lane >> 4, l = lane & 15;
    const int p = blockIdx.x * 16 + warp * 2 + half;
    const int c = l << 2;

    float4 y = {0.f, 0.f, 0.f, 0.f};
#pragma unroll
    for (int kz = 0; kz < 16; ++kz) {
        float4 v = *(const float4*)(g_part + ((size_t)kz * 4096 + p) * 64 + c);
        y.x += v.x; y.y += v.y; y.z += v.z; y.w += v.w;
    }
    float v = fmaxf(fmaf(g_scale1[c + 0], y.x, g_shift1[c + 0]), 0.f) * g_w2[c + 0] +
              fmaxf(fmaf(g_scale1[c + 1], y.y, g_shift1[c + 1]), 0.f) * g_w2[c + 1] +
              fmaxf(fmaf(g_scale1[c + 2], y.z, g_shift1[c + 2]), 0.f) * g_w2[c + 2] +
              fmaxf(fmaf(g_scale1[c + 3], y.w, g_shift1[c + 3]), 0.f) * g_w2[c + 3];
    float tv = g_pt[l * 4096 + p];  // lane l carries kz=l partial
#pragma unroll
    for (int o = 8; o; o >>= 1) {
        v += __shfl_xor_sync(0xffffffffu, v, o);
        tv += __shfl_xor_sync(0xffffffffu, tv, o);
    }
    if (l == 0) {
        g_s[p] = v + g_misc[0];
        float t = fmaxf(fmaf(g_misc[1], tv, g_misc[2]), 0.f);
        g_tt[p] = DEV_EPS + t;
    }
}

// ---------------- softmax: warp-per-row, register logits, MUFU fast path ----------------
// Max recomputed EVERY iteration — required: with a near-one-hot row the masked
// logit drops by ~5000; a stale max underflows ALL exps -> s=0 -> NaN.
__global__ __launch_bounds__(256) void softmax_kernel(float* __restrict__ out) {
    const int w = threadIdx.x >> 5, lane = threadIdx.x & 31;
    const int r = blockIdx.x * 8 + w;
    const int b = r >> 10, i = r & 1023;
    const float si = g_s[r];
    const float invt = 1.0f / g_tt[r];
    const float c = invt * 1.4426950408889634f;

    float l2[32];
#pragma unroll
    for (int q = 0; q < 8; ++q) {
        int j = (q << 7) + (lane << 2);
        float4 s4 = *(const float4*)(g_s + (b << 10) + j);
        float sv[4] = {s4.x, s4.y, s4.z, s4.w};
#pragma unroll
        for (int u = 0; u < 4; ++u) {
            float d = si - sv[u];
            float val = -d * d;
            if (j + u == i) val -= 1000.0f;
            l2[q * 4 + u] = val * c;
        }
    }

    const size_t rbase = ((size_t)b << 20) + ((size_t)i << 10);
#pragma unroll 1
    for (int it = 0; it < 4; ++it) {
        float m = l2[0];
#pragma unroll
        for (int q = 1; q < 32; ++q) m = fmaxf(m, l2[q]);
#pragma unroll
        for (int o = 16; o; o >>= 1) m = fmaxf(m, __shfl_xor_sync(0xffffffffu, m, o));
        float e[32];
        float s = 0.f;
#pragma unroll
        for (int q = 0; q < 32; ++q) {
            e[q] = ex2a(l2[q] - m);
            s += e[q];
        }
#pragma unroll
        for (int o = 16; o; o >>= 1) s += __shfl_xor_sync(0xffffffffu, s, o);
        float invS = 1.0f / s;
        float* op = out + (((size_t)it) << 22) + rbase + (lane << 2);
#pragma unroll
        for (int q = 0; q < 8; ++q) {
            float4 po;
            po.x = e[q * 4 + 0] * invS;
            po.y = e[q * 4 + 1] * invS;
            po.z = e[q * 4 + 2] * invS;
            po.w = e[q * 4 + 3] * invS;
            __stcs((float4*)(op + (q << 7)), po);
        }
        if (it < 3) {
#pragma unroll
            for (int q = 0; q < 32; ++q) {
                float pr = e[q] * invS;
                float om = fmaxf(1.0f - pr, 1e-38f);
                l2[q] += lg2a(om) * invt;
            }
        }
    }
}

// ---------------- launch ----------------
extern "C" void kernel_launch(void* const* d_in, const int* in_sizes, int n_in,
                              void* d_out, int out_size) {
    const float* x = (const float*)d_in[0];
    const float* conv1_w = (const float*)d_in[1];
    const float* conv1_b = (const float*)d_in[2];
    const float* bn1_g = (const float*)d_in[3];
    const float* bn1_b = (const float*)d_in[4];
    const float* bn1_m = (const float*)d_in[5];
    const float* bn1_v = (const float*)d_in[6];
    const float* conv2_w = (const float*)d_in[7];
    const float* conv2_b = (const float*)d_in[8];
    const float* tconv_w = (const float*)d_in[9];
    const float* tconv_b = (const float*)d_in[10];
    const float* bnt_g = (const float*)d_in[11];
    const float* bnt_b = (const float*)d_in[12];
    const float* bnt_m = (const float*)d_in[13];
    const float* bnt_v = (const float*)d_in[14];
    float* out = (float*)d_out;

    static int smem_set = 0;
    if (!smem_set) {
        cudaFuncSetAttribute(gemm_kernel,
                             cudaFuncAttributeMaxDynamicSharedMemorySize, DYN_SMEM);
        smem_set = 1;
    }

    prep_wd_kernel<<<2048, 256>>>(conv1_w);
    prep_small_kernel<<<1, 64>>>(conv1_b, bn1_g, bn1_b, bn1_m, bn1_v,
                                 conv2_w, conv2_b, tconv_b, bnt_g, bnt_b, bnt_m, bnt_v);
    dim3 g(32, 16);
    gemm_kernel<<<g, 128, DYN_SMEM>>>(x, tconv_w);
    epi_kernel<<<256, 256>>>();
    softmax_kernel<<<512, 256>>>(out);
}

// round 13
// speedup vs baseline: 1.2226x; 1.0222x over previous
#include <cuda_runtime.h>
#include <math.h>
#include <stdint.h>

#define DEV_EPS 0.025f

// ---------------- device scratch ----------------
__device__ float g_Wd[4096 * 128];        // dup'd weights: [k][128] = (w,w) pairs, quad-interleaved
__device__ float g_part[16 * 4096 * 64];  // k-split GEMM partials [kz][patch][ch]
__device__ float g_pt[16 * 4096];         // k-split tconv partials [kz][patch]
__device__ float g_s[4096];               // channel-summed metric per patch
__device__ float g_tt[4096];              // DEV_EPS + t per patch
__device__ float g_scale1[64];
__device__ float g_shift1[64];
__device__ float g_w2[64];
__device__ float g_misc[4];               // [0]=b2 [1]=scale_t [2]=shift_t

__device__ __forceinline__ float ex2a(float x) {
    float y; asm("ex2.approx.ftz.f32 %0, %1;" : "=f"(y) : "f"(x)); return y;
}
__device__ __forceinline__ float lg2a(float x) {
    float y; asm("lg2.approx.f32 %0, %1;" : "=f"(y) : "f"(x)); return y;
}
__device__ __forceinline__ void cpa16(uint32_t dst, const void* src) {
    asm volatile("cp.async.cg.shared.global [%0], [%1], 16;" :: "r"(dst), "l"(src));
}

// ---------------- prep: duplicate+interleave conv1 weights ----------------
__global__ void prep_wd_kernel(const float* __restrict__ conv1_w) {
    int idx = blockIdx.x * blockDim.x + threadIdx.x;  // 524288
    int k = idx >> 7, f = idx & 127;
    int q = f >> 5, cg = (f >> 2) & 7, e = f & 3;
    int ch = 8 * cg + 2 * q + (e >> 1);
    g_Wd[idx] = conv1_w[ch * 4096 + k];
}

// ---------------- prep: BN folding + conv2 channel-sum ----------------
__global__ void prep_small_kernel(const float* __restrict__ conv1_b,
                                  const float* __restrict__ bn1_g,
                                  const float* __restrict__ bn1_b,
                                  const float* __restrict__ bn1_m,
                                  const float* __restrict__ bn1_v,
                                  const float* __restrict__ conv2_w,
                                  const float* __restrict__ conv2_b,
                                  const float* __restrict__ tconv_b,
                                  const float* __restrict__ bnt_g,
                                  const float* __restrict__ bnt_b,
                                  const float* __restrict__ bnt_m,
                                  const float* __restrict__ bnt_v) {
    int ch = threadIdx.x;
    if (ch < 64) {
        float inv = 1.0f / sqrtf(bn1_v[ch] + 1e-5f);
        float sc = bn1_g[ch] * inv;
        g_scale1[ch] = sc;
        g_shift1[ch] = sc * (conv1_b[ch] - bn1_m[ch]) + bn1_b[ch];
        float w2 = 0.f;
        for (int cl = 0; cl < 64; ++cl) w2 += conv2_w[cl * 64 + ch];
        g_w2[ch] = w2;
    }
    if (ch == 0) {
        float b2 = 0.f;
        for (int cl = 0; cl < 64; ++cl) b2 += conv2_b[cl];
        g_misc[0] = b2;
        float it = 1.0f / sqrtf(bnt_v[0] + 1e-5f);
        float st = bnt_g[0] * it;
        g_misc[1] = st;
        g_misc[2] = st * (tconv_b[0] - bnt_m[0]) + bnt_b[0];
    }
}

// ---------------- patch GEMM + fused temperature head ----------------
// Grid (32 mtiles, 16 kz), 128 threads, 4 CTAs/SM.
// 16 chunks of 16 k. A smem [k][128] (reg prefetch, __ldcs streaming),
// W smem [k][128] dup'd (cp.async). Inner k: 6 LDS.128 + 32 FFMA2, no MOVs.
#define ATILE (16 * 128)
#define WTILE (16 * 128)
#define TWOFF (2 * ATILE + 2 * WTILE)
#define DYN_SMEM ((TWOFF + 256) * 4)  // 33792 B

extern __shared__ float smg[];

__global__ __launch_bounds__(128, 4) void gemm_kernel(const float* __restrict__ x,
                                                      const float* __restrict__ tw) {
    const int tid = threadIdx.x;
    const int mtile = blockIdx.x, kz = blockIdx.y;
    const int pg = tid >> 3;  // 0..15 -> patches pg*8..+7
    const int cg = tid & 7;   // 0..7  -> channels cg*8..+7

    const int p = (mtile << 7) + tid;
    const int b = p >> 10, py = (p >> 5) & 31, px = p & 31;
    const float* xp = x + ((size_t)b << 22) + (py << 11) + (px << 3);

    float* As = smg;
    float* Ws = smg + 2 * ATILE;
    float* tws = smg + TWOFF;
    uint32_t wsb, twb;
    asm("{ .reg .u64 t; cvta.to.shared.u64 t, %1; cvt.u32.u64 %0, t; }"
        : "=r"(wsb) : "l"(Ws));
    asm("{ .reg .u64 t; cvta.to.shared.u64 t, %1; cvt.u32.u64 %0, t; }"
        : "=r"(twb) : "l"(tws));

    unsigned long long acc[4][8];
#pragma unroll
    for (int q = 0; q < 4; ++q)
#pragma unroll
        for (int j = 0; j < 8; ++j) acc[q][j] = 0ull;
    float tacc = 0.f;

    float4 pa[4];
    int koff = kz << 8;

// streaming (evict-first) x loads: read-once data must not evict g_part/g_Wd from L2
#define LDA(KO)                                                              \
    {                                                                        \
        const int _ko = (KO);                                                \
        const float* xc = xp + ((_ko >> 6) << 16) + (((_ko >> 3) & 7) << 8); \
        _Pragma("unroll")                                                    \
        for (int m = 0; m < 4; ++m)                                          \
            pa[m] = __ldcs((const float4*)(xc + ((m >> 1) << 8) + ((m & 1) << 2))); \
    }
#define LDW(KO, BUF)                                                         \
    {                                                                        \
        const float* wg = g_Wd + (size_t)(KO) * 128;                         \
        const uint32_t wd = wsb + (uint32_t)(BUF) * (WTILE * 4);             \
        _Pragma("unroll")                                                    \
        for (int r = 0; r < 4; ++r)                                          \
            cpa16(wd + (uint32_t)(tid + 128 * r) * 16u, wg + (tid + 128 * r) * 4); \
        asm volatile("cp.async.commit_group;");                              \
    }

    LDA(koff);
    // tw slice FIRST so it joins LDW's commit group (G0), waited before cc=0 use.
    if (tid < 64) cpa16(twb + (uint32_t)tid * 16u, tw + (kz << 8) + tid * 4);
    LDW(koff, 0);

    for (int cc = 0; cc < 16; ++cc) {
        float* A = As + (cc & 1) * ATILE;
        float* W = Ws + (cc & 1) * WTILE;
#pragma unroll
        for (int m = 0; m < 4; ++m) {
            int kl = ((m >> 1) << 3) + ((m & 1) << 2);
            A[(kl + 0) * 128 + tid] = pa[m].x;
            A[(kl + 1) * 128 + tid] = pa[m].y;
            A[(kl + 2) * 128 + tid] = pa[m].z;
            A[(kl + 3) * 128 + tid] = pa[m].w;
        }
        asm volatile("cp.async.wait_group 0;");
        __syncthreads();

        // fused temperature dot: uses this chunk's pa before it is overwritten
        {
            const float* twc = tws + (cc << 4);
#pragma unroll
            for (int m = 0; m < 4; ++m) {
                int kl = ((m >> 1) << 3) + ((m & 1) << 2);
                tacc = fmaf(pa[m].x, twc[kl + 0], tacc);
                tacc = fmaf(pa[m].y, twc[kl + 1], tacc);
                tacc = fmaf(pa[m].z, twc[kl + 2], tacc);
                tacc = fmaf(pa[m].w, twc[kl + 3], tacc);
            }
        }

        if (cc < 15) {
            LDA(koff + 16);
            LDW(koff + 16, (cc + 1) & 1);
        }
        koff += 16;

#pragma unroll 8
        for (int k = 0; k < 16; ++k) {
            const float* ar = &A[(k << 7) + (pg << 3)];
            ulonglong2 a01 = *(const ulonglong2*)ar;
            ulonglong2 a23 = *(const ulonglong2*)(ar + 4);
            const float* wr = &W[(k << 7) + (cg << 2)];
            ulonglong2 wq0 = *(const ulonglong2*)wr;
            ulonglong2 wq1 = *(const ulonglong2*)(wr + 32);
            ulonglong2 wq2 = *(const ulonglong2*)(wr + 64);
            ulonglong2 wq3 = *(const ulonglong2*)(wr + 96);
            unsigned long long aq[4] = {a01.x, a01.y, a23.x, a23.y};
            unsigned long long wp[8] = {wq0.x, wq0.y, wq1.x, wq1.y,
                                        wq2.x, wq2.y, wq3.x, wq3.y};
#pragma unroll
            for (int q = 0; q < 4; ++q)
#pragma unroll
                for (int j = 0; j < 8; ++j)
                    asm("fma.rn.f32x2 %0, %1, %2, %0;"
                        : "+l"(acc[q][j]) : "l"(aq[q]), "l"(wp[j]));
        }
    }

    // store GEMM partials: acc[q][j] = (patch 2q, 2q+1) of pg*8, channel cg*8+j
#pragma unroll
    for (int q = 0; q < 4; ++q) {
        int p0 = (mtile << 7) + (pg << 3) + 2 * q;
        float* d0 = g_part + ((size_t)kz * 4096 + p0) * 64 + (cg << 3);
        float* d1 = d0 + 64;
        float4 lo0, lo1, hi0, hi1;
        lo0.x = __uint_as_float((uint32_t)acc[q][0]);
        lo0.y = __uint_as_float((uint32_t)acc[q][1]);
        lo0.z = __uint_as_float((uint32_t)acc[q][2]);
        lo0.w = __uint_as_float((uint32_t)acc[q][3]);
        lo1.x = __uint_as_float((uint32_t)acc[q][4]);
        lo1.y = __uint_as_float((uint32_t)acc[q][5]);
        lo1.z = __uint_as_float((uint32_t)acc[q][6]);
        lo1.w = __uint_as_float((uint32_t)acc[q][7]);
        hi0.x = __uint_as_float((uint32_t)(acc[q][0] >> 32));
        hi0.y = __uint_as_float((uint32_t)(acc[q][1] >> 32));
        hi0.z = __uint_as_float((uint32_t)(acc[q][2] >> 32));
        hi0.w = __uint_as_float((uint32_t)(acc[q][3] >> 32));
        hi1.x = __uint_as_float((uint32_t)(acc[q][4] >> 32));
        hi1.y = __uint_as_float((uint32_t)(acc[q][5] >> 32));
        hi1.z = __uint_as_float((uint32_t)(acc[q][6] >> 32));
        hi1.w = __uint_as_float((uint32_t)(acc[q][7] >> 32));
        *(float4*)d0 = lo0;
        *(float4*)(d0 + 4) = lo1;
        *(float4*)d1 = hi0;
        *(float4*)(d1 + 4) = hi1;
    }
    g_pt[kz * 4096 + p] = tacc;
}

// ---------------- epilogue v3: warp-per-patch, grid 512 ----------------
// lane l: h = l>>4 (kz half: kz h*8..h*8+7), c = (l&15)*4 (channel quad).
// 8 LDG.128 per lane; xor-16 combines kz halves; 4 shfls reduce channels.
__global__ __launch_bounds__(256) void epi_kernel() {
    const int warp = threadIdx.x >> 5, lane = threadIdx.x & 31;
    const int h = lane >> 4, l = lane & 15;
    const int p = blockIdx.x * 8 + warp;
    const int c = l << 2;

    float4 y = {0.f, 0.f, 0.f, 0.f};
#pragma unroll
    for (int i = 0; i < 8; ++i) {
        int kz = h * 8 + i;
        float4 v = *(const float4*)(g_part + ((size_t)kz * 4096 + p) * 64 + c);
        y.x += v.x; y.y += v.y; y.z += v.z; y.w += v.w;
    }
    // combine kz halves across the xor-16 pair
    y.x += __shfl_xor_sync(0xffffffffu, y.x, 16);
    y.y += __shfl_xor_sync(0xffffffffu, y.y, 16);
    y.z += __shfl_xor_sync(0xffffffffu, y.z, 16);
    y.w += __shfl_xor_sync(0xffffffffu, y.w, 16);

    float v = fmaxf(fmaf(g_scale1[c + 0], y.x, g_shift1[c + 0]), 0.f) * g_w2[c + 0] +
              fmaxf(fmaf(g_scale1[c + 1], y.y, g_shift1[c + 1]), 0.f) * g_w2[c + 1] +
              fmaxf(fmaf(g_scale1[c + 2], y.z, g_shift1[c + 2]), 0.f) * g_w2[c + 2] +
              fmaxf(fmaf(g_scale1[c + 3], y.w, g_shift1[c + 3]), 0.f) * g_w2[c + 3];
    float tv = g_pt[lane * 4096 + p];  // lane carries kz=lane partial (lanes 16-31: kz 16.. none)
    // g_pt has 16 kz entries; lanes 16-31 would read OOB — mask them.
    tv = (lane < 16) ? tv : 0.f;
    tv += __shfl_xor_sync(0xffffffffu, tv, 16);
#pragma unroll
    for (int o = 8; o; o >>= 1) {
        v += __shfl_xor_sync(0xffffffffu, v, o);
        tv += __shfl_xor_sync(0xffffffffu, tv, o);
    }
    if (lane == 0) {
        g_s[p] = v + g_misc[0];
        float t = fmaxf(fmaf(g_misc[1], tv, g_misc[2]), 0.f);
        g_tt[p] = DEV_EPS + t;
    }
}

// ---------------- softmax: warp-per-row, register logits, MUFU fast path ----------------
// Max recomputed EVERY iteration (stale max underflows all exps on one-hot rows -> NaN).
__global__ __launch_bounds__(256) void softmax_kernel(float* __restrict__ out) {
    const int w = threadIdx.x >> 5, lane = threadIdx.x & 31;
    const int r = blockIdx.x * 8 + w;
    const int b = r >> 10, i = r & 1023;
    const float si = g_s[r];
    const float invt = 1.0f / g_tt[r];
    const float c = invt * 1.4426950408889634f;

    float l2[32];
#pragma unroll
    for (int q = 0; q < 8; ++q) {
        int j = (q << 7) + (lane << 2);
        float4 s4 = *(const float4*)(g_s + (b << 10) + j);
        float sv[4] = {s4.x, s4.y, s4.z, s4.w};
#pragma unroll
        for (int u = 0; u < 4; ++u) {
            float d = si - sv[u];
            float val = -d * d;
            if (j + u == i) val -= 1000.0f;
            l2[q * 4 + u] = val * c;
        }
    }

    const size_t rbase = ((size_t)b << 20) + ((size_t)i << 10);
#pragma unroll 1
    for (int it = 0; it < 4; ++it) {
        float m = l2[0];
#pragma unroll
        for (int q = 1; q < 32; ++q) m = fmaxf(m, l2[q]);
#pragma unroll
        for (int o = 16; o; o >>= 1) m = fmaxf(m, __shfl_xor_sync(0xffffffffu, m, o));
        float e[32];
        float s = 0.f;
#pragma unroll
        for (int q = 0; q < 32; ++q) {
            e[q] = ex2a(l2[q] - m);
            s += e[q];
        }
#pragma unroll
        for (int o = 16; o; o >>= 1) s += __shfl_xor_sync(0xffffffffu, s, o);
        float invS = 1.0f / s;
        float* op = out + (((size_t)it) << 22) + rbase + (lane << 2);
#pragma unroll
        for (int q = 0; q < 8; ++q) {
            float4 po;
            po.x = e[q * 4 + 0] * invS;
            po.y = e[q * 4 + 1] * invS;
            po.z = e[q * 4 + 2] * invS;
            po.w = e[q * 4 + 3] * invS;
            __stcs((float4*)(op + (q << 7)), po);
        }
        if (it < 3) {
#pragma unroll
            for (int q = 0; q < 32; ++q) {
                float pr = e[q] * invS;
                float om = fmaxf(1.0f - pr, 1e-38f);
                l2[q] += lg2a(om) * invt;
            }
        }
    }
}

// ---------------- launch ----------------
extern "C" void kernel_launch(void* const* d_in, const int* in_sizes, int n_in,
                              void* d_out, int out_size) {
    const float* x = (const float*)d_in[0];
    const float* conv1_w = (const float*)d_in[1];
    const float* conv1_b = (const float*)d_in[2];
    const float* bn1_g = (const float*)d_in[3];
    const float* bn1_b = (const float*)d_in[4];
    const float* bn1_m = (const float*)d_in[5];
    const float* bn1_v = (const float*)d_in[6];
    const float* conv2_w = (const float*)d_in[7];
    const float* conv2_b = (const float*)d_in[8];
    const float* tconv_w = (const float*)d_in[9];
    const float* tconv_b = (const float*)d_in[10];
    const float* bnt_g = (const float*)d_in[11];
    const float* bnt_b = (const float*)d_in[12];
    const float* bnt_m = (const float*)d_in[13];
    const float* bnt_v = (const float*)d_in[14];
    float* out = (float*)d_out;

    static int smem_set = 0;
    if (!smem_set) {
        cudaFuncSetAttribute(gemm_kernel,
                             cudaFuncAttributeMaxDynamicSharedMemorySize, DYN_SMEM);
        smem_set = 1;
    }

    prep_wd_kernel<<<2048, 256>>>(conv1_w);
    prep_small_kernel<<<1, 64>>>(conv1_b, bn1_g, bn1_b, bn1_m, bn1_v,
                                 conv2_w, conv2_b, tconv_b, bnt_g, bnt_b, bnt_m, bnt_v);
    dim3 g(32, 16);
    gemm_kernel<<<g, 128, DYN_SMEM>>>(x, tconv_w);
    epi_kernel<<<512, 256>>>();
    softmax_kernel<<<512, 256>>>(out);
}